// round 13
// baseline (speedup 1.0000x reference)
#include <cuda_runtime.h>
#include <cuda_bf16.h>
#include <cstdint>

// VectorQuantizer: warp-level bf16 mma.sync prune + exact fp32 rescore.
// out = [ z_q (2097152 f32) | loss (1 f32) | indices (32768 f32) ]

#define C_DIM    64
#define K_CB     1024
#define P_BLK    256
#define NT       256
#define Z_ELEMS  2097152
#define N_PIX    32768
#define GRID_MAIN (N_PIX / P_BLK)   // 128
#define NTILES   8                  // 8 tiles x 128 codes
#define CAP      8

// ---- device scratch ----
__device__ float    g_Et[C_DIM * K_CB];   // transposed codebook [c][k]
__device__ uint2    g_Efrag[128 * 4 * 32];// bf16 B-fragments [chunk][jp][lane]
__device__ float    g_e2[K_CB];           // sum e^2 (sequential c)
__device__ float    g_z2[N_PIX];          // sum z^2 (sequential c)
__device__ float    g_S[N_PIX];           // sum |z|
__device__ double   g_sum;
__device__ unsigned g_ticket;

__device__ __forceinline__ uint32_t pk_bf16x2(float lo, float hi) {
    uint32_t r;
    asm("cvt.rn.bf16x2.f32 %0, %1, %2;" : "=r"(r) : "f"(hi), "f"(lo));
    return r;
}
__device__ __forceinline__ void mma_bf16(float* c, const uint32_t* a,
                                         uint32_t b0, uint32_t b1) {
    asm("mma.sync.aligned.m16n8k16.row.col.f32.bf16.bf16.f32 "
        "{%0,%1,%2,%3}, {%4,%5,%6,%7}, {%8,%9}, {%0,%1,%2,%3};"
        : "+f"(c[0]), "+f"(c[1]), "+f"(c[2]), "+f"(c[3])
        : "r"(a[0]), "r"(a[1]), "r"(a[2]), "r"(a[3]), "r"(b0), "r"(b1));
}
__device__ __forceinline__ void cp16(unsigned s, const void* g) {
    asm volatile("cp.async.ca.shared.global [%0], [%1], 16;\n" :: "r"(s), "l"(g));
}
__device__ __forceinline__ void cp_commit() { asm volatile("cp.async.commit_group;\n"); }
__device__ __forceinline__ void cp_wait0()  { asm volatile("cp.async.wait_group 0;\n"); }

// ---------------------------------------------------------------------------
// Prep: Et transpose, bf16 B-fragments, e2, z2, S, resets.
// ---------------------------------------------------------------------------
__global__ void vq_prep(const float* __restrict__ cb, const float* __restrict__ z) {
    int id = blockIdx.x * blockDim.x + threadIdx.x;
    if (id == 0) { g_sum = 0.0; g_ticket = 0u; }

    if (id < 16384) {
        // transpose g_Et
        int k  = id >> 4;
        int c4 = (id & 15) * 4;
        float4 v = *(const float4*)(cb + k * 64 + c4);
        g_Et[(c4 + 0) * 1024 + k] = v.x;
        g_Et[(c4 + 1) * 1024 + k] = v.y;
        g_Et[(c4 + 2) * 1024 + k] = v.z;
        g_Et[(c4 + 3) * 1024 + k] = v.w;

        // B-fragment pack: id = C*128 + jp*32 + L
        int C  = id >> 7;
        int r7 = id & 127;
        int jp = r7 >> 5;
        int L  = r7 & 31;
        int m  = L & 3;
        int code = C * 8 + (L >> 2);
        const float* e = cb + code * 64;
        int ka = 16 * jp + 2 * m;      // .x: k rows 2m,2m+1
        int kb = ka + 8;               // .y: k rows 2m+8,2m+9
        __nv_bfloat16 a0 = __float2bfloat16(e[ka]),     a1 = __float2bfloat16(e[ka + 1]);
        __nv_bfloat16 b0 = __float2bfloat16(e[kb]),     b1 = __float2bfloat16(e[kb + 1]);
        uint2 u;
        u.x = (uint32_t)__bfloat16_as_ushort(a0) | ((uint32_t)__bfloat16_as_ushort(a1) << 16);
        u.y = (uint32_t)__bfloat16_as_ushort(b0) | ((uint32_t)__bfloat16_as_ushort(b1) << 16);
        g_Efrag[id] = u;
    }
    if (id < 1024) {                   // e2: strict sequential c
        const float* row = cb + id * 64;
        float s = 0.f;
        #pragma unroll
        for (int c = 0; c < 64; c++)
            s = __fadd_rn(s, __fmul_rn(row[c], row[c]));
        g_e2[id] = s;
    }
    if (id >= 16384 && id < 16384 + N_PIX) {   // z2 (seq c) + S
        int n = id - 16384;
        int b = n >> 10, p = n & 1023;
        const float* zp = z + (size_t)b * 65536 + p;
        float s = 0.f, sa = 0.f;
        #pragma unroll
        for (int c = 0; c < 64; c++) {
            float v = zp[c * 1024];
            s  = __fadd_rn(s, __fmul_rn(v, v));
            sa = __fadd_rn(sa, fabsf(v));
        }
        g_z2[n] = s;
        g_S[n]  = sa;
    }
}

// ---------------------------------------------------------------------------
// smem byte offsets
#define SO_ZT    0                         // 256*65*4 = 66560
#define SO_EF    66560                     // 2*16384  = 32768
#define SO_E2    99328                     // 4096
#define SO_TMIN  103424                    // 8*256*4 = 8192
#define SO_CAND  111616                    // 256*8*4 = 8192
#define SO_CNT   119808                    // 1024
#define SO_WIN   120832                    // 1024
#define SO_RED   121856                    // 64
#define SM_TOTAL 121920

__global__ __launch_bounds__(NT, 1)
void vq_main(const float* __restrict__ z, const float* __restrict__ cb,
             float* __restrict__ out) {
    extern __shared__ char sm[];
    float*  sZt   = (float*)(sm + SO_ZT);     // [256 px][65] exact fp32 z
    uint2*  sEf   = (uint2*)(sm + SO_EF);     // [2 buf][2048] B-frags
    float*  sE2   = (float*)(sm + SO_E2);     // [1024]
    float*  sTmin = (float*)(sm + SO_TMIN);   // [8 tiles][256 px]
    int*    sCand = (int*)(sm + SO_CAND);
    int*    sCnt  = (int*)(sm + SO_CNT);
    int*    sWin  = (int*)(sm + SO_WIN);
    double* sRed  = (double*)(sm + SO_RED);

    const int tid  = threadIdx.x;
    const int wid  = tid >> 5;
    const int lane = tid & 31;
    const int g    = lane >> 2;
    const int m    = lane & 3;
    const int pxw  = wid * 32;
    const int n0   = blockIdx.x * P_BLK;
    const int b    = n0 >> 10;
    const int p0   = n0 & 1023;
    const float* zb = z + (size_t)b * 65536 + p0;

    const unsigned uF = (unsigned)__cvta_generic_to_shared(sEf);

    // prefetch B-frag tile 0 (16KB)
    #pragma unroll
    for (int j = 0; j < 4; j++) {
        int f = tid + j * NT;
        cp16(uF + (unsigned)f * 16u, (const char*)g_Efrag + f * 16);
    }
    cp_commit();

    // stage exact z: gmem [c][1024] -> sZt [px][65] (conflict-free both ways)
    for (int i = tid; i < 64 * 256; i += NT) {
        int c = i >> 8, px = i & 255;
        sZt[px * 65 + c] = zb[c * 1024 + px];
    }
    *(float4*)(sE2 + tid * 4) = *(const float4*)(g_e2 + tid * 4);
    sCnt[tid] = 0;
    __syncthreads();

    // build A fragments (z -> bf16), resident for all code tiles
    uint32_t A[2][4][4];
    #pragma unroll
    for (int t2 = 0; t2 < 2; t2++) {
        int ra = pxw + t2 * 16 + g, rb = ra + 8;
        #pragma unroll
        for (int ks = 0; ks < 4; ks++) {
            int k0 = ks * 16 + 2 * m;
            A[t2][ks][0] = pk_bf16x2(sZt[ra * 65 + k0],     sZt[ra * 65 + k0 + 1]);
            A[t2][ks][1] = pk_bf16x2(sZt[rb * 65 + k0],     sZt[rb * 65 + k0 + 1]);
            A[t2][ks][2] = pk_bf16x2(sZt[ra * 65 + k0 + 8], sZt[ra * 65 + k0 + 9]);
            A[t2][ks][3] = pk_bf16x2(sZt[rb * 65 + k0 + 8], sZt[rb * 65 + k0 + 9]);
        }
    }

    float sz[4], wv[4], mn[4], thr[4];
    #pragma unroll
    for (int i = 0; i < 4; i++) {
        int r = n0 + pxw + g + 8 * i;
        sz[i] = g_z2[r];
        wv[i] = __fmaf_rn(g_S[r], 2e-5f, 1e-4f);   // = 2W (2-sided window)
        mn[i] = 3.4e38f;
        thr[i] = 0.f;
    }

    // ---- two-pass scan over 8 tiles x 128 codes ----
    for (int it = 0; it < 16; ++it) {
        const int tt = it & 7;
        cp_wait0();
        __syncthreads();
        if (it + 1 < 16) {
            unsigned dst = uF + (unsigned)(((it + 1) & 1) * 16384);
            const char* src = (const char*)g_Efrag + ((it + 1) & 7) * 16384;
            #pragma unroll
            for (int j = 0; j < 4; j++) {
                int f = tid + j * NT;
                cp16(dst + (unsigned)f * 16u, src + f * 16);
            }
            cp_commit();
        }
        const uint2* fb = sEf + (it & 1) * 2048;
        const bool p2 = (it >= 8);

        bool skip = false;
        if (p2) {
            bool any = (sTmin[tt * 256 + pxw + g]      <= thr[0]) ||
                       (sTmin[tt * 256 + pxw + g + 8]  <= thr[1]) ||
                       (sTmin[tt * 256 + pxw + g + 16] <= thr[2]) ||
                       (sTmin[tt * 256 + pxw + g + 24] <= thr[3]);
            skip = !__any_sync(0xffffffffu, any);
        }

        float tmn[4] = { 3.4e38f, 3.4e38f, 3.4e38f, 3.4e38f };
        if (!skip) {
            #pragma unroll 2
            for (int CH = 0; CH < 8; ++CH) {
                const int chA = CH * 2, chB = chA + 1;
                uint2 bA[4], bB[4];
                #pragma unroll
                for (int jp = 0; jp < 4; jp++) {
                    bA[jp] = fb[(chA * 4 + jp) * 32 + lane];
                    bB[jp] = fb[(chB * 4 + jp) * 32 + lane];
                }
                float acc[4][4];
                #pragma unroll
                for (int q = 0; q < 4; q++)
                    #pragma unroll
                    for (int j = 0; j < 4; j++) acc[q][j] = 0.f;
                #pragma unroll
                for (int ks = 0; ks < 4; ks++) {
                    mma_bf16(acc[0], A[0][ks], bA[ks].x, bA[ks].y);
                    mma_bf16(acc[1], A[1][ks], bA[ks].x, bA[ks].y);
                    mma_bf16(acc[2], A[0][ks], bB[ks].x, bB[ks].y);
                    mma_bf16(acc[3], A[1][ks], bB[ks].x, bB[ks].y);
                }
                const int kbA = tt * 128 + chA * 8 + 2 * m;
                const int kbB = kbA + 8;
                float2 eA = *(const float2*)(sE2 + kbA);
                float2 eB = *(const float2*)(sE2 + kbB);
                float d[16];
                d[0]  = fmaf(acc[0][0], -2.f, sz[0] + eA.x);  // r0, kbA
                d[1]  = fmaf(acc[0][1], -2.f, sz[0] + eA.y);  // r0, kbA+1
                d[2]  = fmaf(acc[0][2], -2.f, sz[1] + eA.x);  // r1
                d[3]  = fmaf(acc[0][3], -2.f, sz[1] + eA.y);
                d[4]  = fmaf(acc[1][0], -2.f, sz[2] + eA.x);  // r2
                d[5]  = fmaf(acc[1][1], -2.f, sz[2] + eA.y);
                d[6]  = fmaf(acc[1][2], -2.f, sz[3] + eA.x);  // r3
                d[7]  = fmaf(acc[1][3], -2.f, sz[3] + eA.y);
                d[8]  = fmaf(acc[2][0], -2.f, sz[0] + eB.x);  // r0, kbB
                d[9]  = fmaf(acc[2][1], -2.f, sz[0] + eB.y);
                d[10] = fmaf(acc[2][2], -2.f, sz[1] + eB.x);
                d[11] = fmaf(acc[2][3], -2.f, sz[1] + eB.y);
                d[12] = fmaf(acc[3][0], -2.f, sz[2] + eB.x);
                d[13] = fmaf(acc[3][1], -2.f, sz[2] + eB.y);
                d[14] = fmaf(acc[3][2], -2.f, sz[3] + eB.x);
                d[15] = fmaf(acc[3][3], -2.f, sz[3] + eB.y);

                if (!p2) {
                    tmn[0] = fminf(tmn[0], fminf(fminf(d[0], d[1]),  fminf(d[8],  d[9])));
                    tmn[1] = fminf(tmn[1], fminf(fminf(d[2], d[3]),  fminf(d[10], d[11])));
                    tmn[2] = fminf(tmn[2], fminf(fminf(d[4], d[5]),  fminf(d[12], d[13])));
                    tmn[3] = fminf(tmn[3], fminf(fminf(d[6], d[7]),  fminf(d[14], d[15])));
                } else {
                    const int r0 = pxw + g, r1 = r0 + 8, r2 = r0 + 16, r3 = r0 + 24;
                    #pragma unroll
                    for (int j = 0; j < 16; j++) {
                        int row = (j & 4) ? ((j & 2) ? r3 : r2) : ((j & 2) ? r1 : r0);
                        float th = (j & 4) ? ((j & 2) ? thr[3] : thr[2])
                                           : ((j & 2) ? thr[1] : thr[0]);
                        int kk = ((j & 8) ? kbB : kbA) + (j & 1);
                        if (d[j] <= th) {
                            int pos = atomicAdd(&sCnt[row], 1);
                            if (pos < CAP) sCand[row * CAP + pos] = kk;
                        }
                    }
                }
            }
        }

        if (!p2) {
            #pragma unroll
            for (int i = 0; i < 4; i++) {
                mn[i] = fminf(mn[i], tmn[i]);
                float tq = tmn[i];
                tq = fminf(tq, __shfl_xor_sync(0xffffffffu, tq, 1));
                tq = fminf(tq, __shfl_xor_sync(0xffffffffu, tq, 2));
                if (m == 0) sTmin[tt * 256 + pxw + g + 8 * i] = tq;
            }
            if (it == 7) {
                #pragma unroll
                for (int i = 0; i < 4; i++) {
                    float v = mn[i];
                    v = fminf(v, __shfl_xor_sync(0xffffffffu, v, 1));
                    v = fminf(v, __shfl_xor_sync(0xffffffffu, v, 2));
                    thr[i] = v + wv[i];
                }
            }
        }
    }
    __syncthreads();

    // ---- exact rescore (identical fp32 tree + first-index ties) ----
    {
        const int px = tid;
        const float szp = g_z2[n0 + px];
        const int cv = sCnt[px];
        float bd = 3.4e38f; int bk = 0;
        if (cv <= CAP) {
            for (int i = 0; i < cv; i++) {
                int k = sCand[px * CAP + i];
                const float* er = cb + k * 64;
                float s = 0.f;
                #pragma unroll
                for (int c = 0; c < 64; c++)
                    s = __fmaf_rn(sZt[px * 65 + c], er[c], s);
                float dd = __fmaf_rn(s, -2.f, __fadd_rn(szp, sE2[k]));
                if (dd < bd || (dd == bd && k < bk)) { bd = dd; bk = k; }
            }
        } else {                       // overflow: full exact scan
            for (int k = 0; k < 1024; k++) {
                const float* er = cb + k * 64;
                float s = 0.f;
                #pragma unroll
                for (int c = 0; c < 64; c++)
                    s = __fmaf_rn(sZt[px * 65 + c], er[c], s);
                float dd = __fmaf_rn(s, -2.f, __fadd_rn(szp, sE2[k]));
                if (dd < bd) { bd = dd; bk = k; }
            }
        }
        sWin[px] = bk;
        out[(size_t)Z_ELEMS + 1 + n0 + px] = (float)bk;
    }
    __syncthreads();

    // ---- epilogue: z_q + loss ----
    double lsum = 0.0;
    for (int i = tid; i < P_BLK * C_DIM; i += NT) {
        int c = i >> 8, px = i & 255;
        int k = sWin[px];
        float ev  = g_Et[c * 1024 + k];
        float zv  = sZt[px * 65 + c];
        float tdf = __fadd_rn(ev, -zv);
        out[(size_t)b * 65536 + c * 1024 + p0 + px] = __fadd_rn(zv, tdf);
        lsum += (double)__fmul_rn(tdf, tdf);
    }
    #pragma unroll
    for (int off = 16; off >= 1; off >>= 1)
        lsum += __shfl_down_sync(0xffffffffu, lsum, off);
    if (lane == 0) sRed[wid] = lsum;
    __syncthreads();

    if (tid == 0) {
        double s = 0.0;
        #pragma unroll
        for (int w = 0; w < 8; w++) s += sRed[w];
        atomicAdd(&g_sum, s);
        __threadfence();
        unsigned tk = atomicAdd(&g_ticket, 1u);
        if (tk == (unsigned)(gridDim.x - 1)) {
            double tot = atomicAdd(&g_sum, 0.0);
            float mf = (float)(tot / (double)Z_ELEMS);
            out[Z_ELEMS] = __fadd_rn(mf, __fmul_rn(0.25f, mf));
        }
    }
}

extern "C" void kernel_launch(void* const* d_in, const int* in_sizes, int n_in,
                              void* d_out, int out_size) {
    const float* z  = (const float*)d_in[0];
    const float* cb = (const float*)d_in[1];
    float* out = (float*)d_out;

    cudaFuncSetAttribute(vq_main, cudaFuncAttributeMaxDynamicSharedMemorySize,
                         SM_TOTAL);
    vq_prep<<<256, 256>>>(cb, z);
    vq_main<<<GRID_MAIN, NT, SM_TOTAL>>>(z, cb, out);
}

// round 15
// speedup vs baseline: 3.4280x; 3.4280x over previous
#include <cuda_runtime.h>
#include <cstdint>

// VectorQuantizer: z[32,64,32,32] fp32, codebook[1024,64] fp32
// out = [ z_q (2097152 f32) | loss (1 f32) | indices (32768 f32) ]
// Scalar FFMA2 path (tensor cores unusable on this toolchain: tcgen05 needs
// sm_103a target; mma.sync is emulated ~40x slower). Persistent CTAs + dup-z.

#define C_DIM    64
#define K_CB     1024
#define P_BLK    64
#define K_TILE   128
#define NT       256
#define Z_ELEMS  2097152
#define N_PIX    32768
#define N_TILES_PX (N_PIX / P_BLK)   // 512 pixel tiles
#define NTILES   (K_CB / K_TILE)     // 8 code tiles
#define GRID_MAIN 296                // persistent: 2 CTAs x 148 SMs

__device__ float    g_Et[C_DIM * K_CB];   // transposed codebook [c][k]
__device__ float    g_e2[K_CB];           // sum(e^2) per code (sequential-c order)
__device__ float    g_z2[N_PIX];          // sum(z^2) per pixel (sequential-c order)
__device__ double   g_sum;
__device__ unsigned g_ticket;
__device__ unsigned g_work;

__device__ __forceinline__ unsigned long long pack2dup(float x) {
    unsigned long long r;
    unsigned int u = __float_as_uint(x);
    asm("mov.b64 %0, {%1, %1};" : "=l"(r) : "r"(u));
    return r;
}
__device__ __forceinline__ void fma2(unsigned long long& d,
                                     unsigned long long a,
                                     unsigned long long b) {
    asm("fma.rn.f32x2 %0, %1, %2, %0;" : "+l"(d) : "l"(a), "l"(b));
}
__device__ __forceinline__ float2 unpack2(unsigned long long v) {
    unsigned int a, b;
    asm("mov.b64 {%0, %1}, %2;" : "=r"(a), "=r"(b) : "l"(v));
    return make_float2(__uint_as_float(a), __uint_as_float(b));
}
__device__ __forceinline__ void cp16(unsigned s, const void* g) {
    asm volatile("cp.async.ca.shared.global [%0], [%1], 16;\n" :: "r"(s), "l"(g));
}
__device__ __forceinline__ void cp_commit() { asm volatile("cp.async.commit_group;\n"); }
__device__ __forceinline__ void cp_wait0()  { asm volatile("cp.async.wait_group 0;\n"); }

// ---------------------------------------------------------------------------
__global__ void vq_prep(const float* __restrict__ cb, const float* __restrict__ z) {
    int id = blockIdx.x * blockDim.x + threadIdx.x;
    if (id == 0) { g_sum = 0.0; g_ticket = 0u; g_work = 0u; }

    if (id < 16384) {            // transpose
        int k  = id >> 4;
        int c4 = (id & 15) * 4;
        float4 v = *(const float4*)(cb + k * 64 + c4);
        g_Et[(c4 + 0) * 1024 + k] = v.x;
        g_Et[(c4 + 1) * 1024 + k] = v.y;
        g_Et[(c4 + 2) * 1024 + k] = v.z;
        g_Et[(c4 + 3) * 1024 + k] = v.w;
    }
    if (id < 1024) {             // e2: strict sequential over c
        const float* row = cb + id * 64;
        float s = 0.f;
        #pragma unroll
        for (int c = 0; c < 64; c++)
            s = __fadd_rn(s, __fmul_rn(row[c], row[c]));
        g_e2[id] = s;
    }
    if (id >= 16384 && id < 16384 + N_PIX) {   // z2: strict sequential over c
        int n = id - 16384;
        int b = n >> 10, p = n & 1023;
        const float* zp = z + (size_t)b * 65536 + p;
        float s = 0.f;
        #pragma unroll
        for (int c = 0; c < 64; c++) {
            float v = zp[c * 1024];
            s = __fadd_rn(s, __fmul_rn(v, v));
        }
        g_z2[n] = s;
    }
}

// ---------------------------------------------------------------------------
// Persistent main: 296 CTAs pull 64-pixel tiles via ticket. Per tile:
// 8 code-tiles of 128 (cp.async double-buffered). Thread: 4px x 8codes.
// z stored as dup f32x2 pairs -> channel inner = 4 LDS.128 + 16 FFMA2, 0 MOVs.
// SW pipeline: channel c+1 loads issued before c's FMA block.
// d = fl( fl(sz+e2) - 2*dot ) replicates the reference expression tree.
// smem layout (8-byte items first after the big arrays so sRed stays aligned):
//   sZd [0, 32768)  sE [32768, 98304)  sRed [98304, 98368)  sIdx [98368, 98624)
//   sTl [98624, 98628)
// ---------------------------------------------------------------------------
__global__ __launch_bounds__(NT, 2)
void vq_main(const float* __restrict__ z, float* __restrict__ out) {
    extern __shared__ char smem_raw[];
    unsigned long long* sZd = (unsigned long long*)smem_raw;     // [64][64] dup, 32KB
    float*  sE   = (float*)(sZd + 64 * 64);                      // [2][64][128] 64KB
    double* sRed = (double*)(sE + 2 * 64 * 128);                 // [8]  (offset 98304, 8-aligned)
    int*    sIdx = (int*)(sRed + 8);                             // [64] (offset 98368)
    int*    sTl  = sIdx + 64;                                    // [1]  (offset 98624)

    const int tid = threadIdx.x;
    const int tx  = tid & 15;
    const int ty  = tid >> 4;          // 0..15
    const int pxb = ty * 4;
    const unsigned sE_base = (unsigned)__cvta_generic_to_shared(sE);

    for (;;) {
        __syncthreads();               // protect sZd/sIdx reuse + sTl
        if (tid == 0) sTl[0] = (int)atomicAdd(&g_work, 1u);
        __syncthreads();
        const int tile = sTl[0];
        if (tile >= N_TILES_PX) break;

        const int n0 = tile * P_BLK;
        const int b  = n0 >> 10;
        const int p0 = n0 & 1023;
        const float* zb = z + (size_t)b * 65536 + p0;

        // prefetch E code-tile 0 into buffer 0
        #pragma unroll
        for (int j = 0; j < 8; j++) {
            int f  = tid + j * NT;
            int c  = f >> 5;
            int k4 = (f & 31) << 2;
            cp16(sE_base + (unsigned)(c * 128 + k4) * 4u, g_Et + c * 1024 + k4);
        }
        cp_commit();

        // load z tile as dup f32x2 pairs
        for (int i = tid; i < 64 * 64; i += NT) {
            int c = i >> 6, px = i & 63;
            sZd[c * 64 + px] = pack2dup(zb[c * 1024 + px]);
        }

        float sz[4];
        #pragma unroll
        for (int p = 0; p < 4; p++) sz[p] = g_z2[n0 + pxb + p];

        float best[4]; int bidx[4];
        #pragma unroll
        for (int p = 0; p < 4; p++) { best[p] = 3.4e38f; bidx[p] = 0; }

        for (int t = 0; t < NTILES; t++) {
            cp_wait0();
            __syncthreads();           // tile t resident; prior compute done

            if (t + 1 < NTILES) {
                unsigned dstb = sE_base + (unsigned)(((t + 1) & 1) * 8192) * 4u;
                const float* srcb = g_Et + (t + 1) * 128;
                #pragma unroll
                for (int j = 0; j < 8; j++) {
                    int f  = tid + j * NT;
                    int c  = f >> 5;
                    int k4 = (f & 31) << 2;
                    cp16(dstb + (unsigned)(c * 128 + k4) * 4u, srcb + c * 1024 + k4);
                }
                cp_commit();
            }

            float4 e2a = *(const float4*)(g_e2 + t * 128 + 4 * tx);
            float4 e2b = *(const float4*)(g_e2 + t * 128 + 64 + 4 * tx);

            unsigned long long acc[4][4];
            #pragma unroll
            for (int p = 0; p < 4; p++)
                #pragma unroll
                for (int q = 0; q < 4; q++) acc[p][q] = 0ull;

            const unsigned long long* zrow = sZd + pxb;
            const float* erow = sE + (t & 1) * 8192 + 4 * tx;

            // ---- software-pipelined channel loop: 4 LDS.128 + 16 FFMA2 ----
            ulonglong2 zr[2][2];       // [stage][2 x ull2 = 4 dup pixels]
            ulonglong2 er[2][2];       // [stage][2 x ull2 = 8 codes]

            zr[0][0] = *(const ulonglong2*)(zrow);
            zr[0][1] = *(const ulonglong2*)(zrow + 2);
            er[0][0] = *(const ulonglong2*)(erow);
            er[0][1] = *(const ulonglong2*)(erow + 64);

            #pragma unroll 8
            for (int c = 0; c < C_DIM; c++) {
                const int cur = c & 1, nxt = cur ^ 1;
                const int nc  = (c + 1) & 63;      // in-bounds dummy at c=63
                zr[nxt][0] = *(const ulonglong2*)(zrow + nc * 64);
                zr[nxt][1] = *(const ulonglong2*)(zrow + nc * 64 + 2);
                er[nxt][0] = *(const ulonglong2*)(erow + nc * 128);
                er[nxt][1] = *(const ulonglong2*)(erow + nc * 128 + 64);

                unsigned long long e0 = er[cur][0].x, e1 = er[cur][0].y;
                unsigned long long e2 = er[cur][1].x, e3 = er[cur][1].y;
                unsigned long long zp[4] = { zr[cur][0].x, zr[cur][0].y,
                                             zr[cur][1].x, zr[cur][1].y };
                #pragma unroll
                for (int p = 0; p < 4; p++) {
                    fma2(acc[p][0], zp[p], e0);
                    fma2(acc[p][1], zp[p], e1);
                    fma2(acc[p][2], zp[p], e2);
                    fma2(acc[p][3], zp[p], e3);
                }
            }

            // d = fl(sz+e2) - 2*dot; strict < keeps first (smallest) index
            float e2v[8] = { e2a.x, e2a.y, e2a.z, e2a.w,
                             e2b.x, e2b.y, e2b.z, e2b.w };
            #pragma unroll
            for (int q = 0; q < 4; q++) {
                int k0 = (q < 2) ? (4 * tx + 2 * q) : (64 + 4 * tx + 2 * (q - 2));
                float e20 = e2v[2 * q], e21 = e2v[2 * q + 1];
                int kg = t * 128 + k0;
                #pragma unroll
                for (int p = 0; p < 4; p++) {
                    float2 dp = unpack2(acc[p][q]);
                    float d0 = __fmaf_rn(dp.x, -2.f, __fadd_rn(sz[p], e20));
                    float d1 = __fmaf_rn(dp.y, -2.f, __fadd_rn(sz[p], e21));
                    if (d0 < best[p]) { best[p] = d0; bidx[p] = kg; }
                    if (d1 < best[p]) { best[p] = d1; bidx[p] = kg + 1; }
                }
            }
        }

        // argmin reduce across the 16 tx lanes
        #pragma unroll
        for (int p = 0; p < 4; p++) {
            float bv = best[p]; int bi = bidx[p];
            #pragma unroll
            for (int off = 8; off >= 1; off >>= 1) {
                float ov = __shfl_xor_sync(0xffffffffu, bv, off);
                int   oi = __shfl_xor_sync(0xffffffffu, bi, off);
                if (ov < bv || (ov == bv && oi < bi)) { bv = ov; bi = oi; }
            }
            if (tx == 0) sIdx[pxb + p] = bi;
        }
        __syncthreads();

        // epilogue: gather, straight-through output, loss partial, indices
        double lsum = 0.0;
        for (int i = tid; i < P_BLK * C_DIM; i += NT) {
            int c = i >> 6, px = i & 63;
            int k = sIdx[px];
            float ev  = g_Et[c * 1024 + k];
            float zv  = __uint_as_float((unsigned)(sZd[c * 64 + px] & 0xffffffffu));
            float tdf = __fadd_rn(ev, -zv);
            out[(size_t)b * 65536 + c * 1024 + p0 + px] = __fadd_rn(zv, tdf);
            lsum += (double)__fmul_rn(tdf, tdf);
        }
        if (tid < P_BLK)
            out[(size_t)Z_ELEMS + 1 + n0 + tid] = (float)sIdx[tid];

        #pragma unroll
        for (int off = 16; off >= 1; off >>= 1)
            lsum += __shfl_down_sync(0xffffffffu, lsum, off);
        if ((tid & 31) == 0) sRed[tid >> 5] = lsum;
        __syncthreads();

        if (tid == 0) {
            double s = 0.0;
            #pragma unroll
            for (int w = 0; w < 8; w++) s += sRed[w];
            atomicAdd(&g_sum, s);
            __threadfence();
            unsigned tk = atomicAdd(&g_ticket, 1u);
            if (tk == (unsigned)(N_TILES_PX - 1)) {
                double tot = atomicAdd(&g_sum, 0.0);
                float mf = (float)(tot / (double)Z_ELEMS);
                out[Z_ELEMS] = __fadd_rn(mf, __fmul_rn(0.25f, mf));
            }
        }
    }
}

extern "C" void kernel_launch(void* const* d_in, const int* in_sizes, int n_in,
                              void* d_out, int out_size) {
    const float* z  = (const float*)d_in[0];
    const float* cb = (const float*)d_in[1];
    float* out = (float*)d_out;

    const int smem_bytes = 64 * 64 * 8 + 2 * 64 * 128 * 4 + 8 * 8 + 64 * 4 + 8;
    cudaFuncSetAttribute(vq_main, cudaFuncAttributeMaxDynamicSharedMemorySize,
                         smem_bytes);

    vq_prep<<<192, 256>>>(cb, z);
    vq_main<<<GRID_MAIN, NT, smem_bytes>>>(z, out);
}